// round 2
// baseline (speedup 1.0000x reference)
#include <cuda_runtime.h>
#include <cuda_bf16.h>

#define HH 1024
#define WW 1024
#define NB 8

// Load 6 consecutive values (cols w0-1 .. w0+4) from row hh of a (HH,WW) plane,
// zero-padded outside. One aligned LDG.128 per lane; halo values come from
// neighbor lanes via warp shuffle. Only lanes 0 / 31 of each warp fall back to
// a predicated scalar load (1 extra cache line per warp instead of 4 per edge).
// hh is warp-uniform (derived from blockIdx.y), so the OOB branch is uniform.
__device__ __forceinline__ void load_row6(const float* __restrict__ base, int hh,
                                          int w0, int lane, float out[6]) {
    if (hh < 0 || hh >= HH) {
#pragma unroll
        for (int c = 0; c < 6; c++) out[c] = 0.0f;
        return;
    }
    const float* row = base + (size_t)hh * WW;
    float4 v = *reinterpret_cast<const float4*>(row + w0);

    float left  = __shfl_up_sync(0xffffffffu, v.w, 1);
    float right = __shfl_down_sync(0xffffffffu, v.x, 1);
    if (lane == 0)  left  = (w0 > 0)       ? row[w0 - 1] : 0.0f;
    if (lane == 31) right = (w0 + 4 < WW)  ? row[w0 + 4] : 0.0f;

    out[0] = left;
    out[1] = v.x; out[2] = v.y; out[3] = v.z; out[4] = v.w;
    out[5] = right;
}

__global__ void __launch_bounds__(128)
small_sm_block_kernel(const float* __restrict__ image,
                      const float* __restrict__ x,
                      const float* __restrict__ wgt,   // (9,1,3,3) = 81
                      const float* __restrict__ bias,  // (9,)
                      float* __restrict__ y) {
    __shared__ float sw[81];
    __shared__ float sb[9];
    int t = threadIdx.x;
    if (t < 81) sw[t] = wgt[t];
    if (t < 9)  sb[t] = bias[t];
    __syncthreads();

    const int lane = t & 31;
    const int h  = blockIdx.y;
    const int w0 = (blockIdx.x * blockDim.x + t) * 4;

    // ---- image neighborhood: rows h-1..h+1, cols w0-1..w0+4 ----
    float img[3][6];
#pragma unroll
    for (int r = 0; r < 3; r++) load_row6(image, h - 1 + r, w0, lane, img[r]);

    // ---- K[j][p] = bias[j] + sum_{a,d} img[a][p+d] * w[j, a, d] ----
    float K[9][4];
#pragma unroll
    for (int j = 0; j < 9; j++) {
        const float bj = sb[j];
#pragma unroll
        for (int p = 0; p < 4; p++) K[j][p] = bj;
#pragma unroll
        for (int a = 0; a < 3; a++) {
#pragma unroll
            for (int d = 0; d < 3; d++) {
                const float wv = sw[j * 9 + a * 3 + d];
#pragma unroll
                for (int p = 0; p < 4; p++) K[j][p] += img[a][p + d] * wv;
            }
        }
    }

    // ---- apply: y[b,h,w0+p] = sum_{a,d} xpad[b,h-1+a,w0+p-1+d] * K[3a+d][p] ----
    const size_t plane = (size_t)HH * WW;
    const size_t orow  = (size_t)h * WW + w0;
#pragma unroll
    for (int b = 0; b < NB; b++) {
        const float* xb = x + (size_t)b * plane;
        float xr[3][6];
#pragma unroll
        for (int r = 0; r < 3; r++) load_row6(xb, h - 1 + r, w0, lane, xr[r]);

        float acc[4] = {0.f, 0.f, 0.f, 0.f};
#pragma unroll
        for (int a = 0; a < 3; a++) {
#pragma unroll
            for (int d = 0; d < 3; d++) {
                const int j = a * 3 + d;
#pragma unroll
                for (int p = 0; p < 4; p++) acc[p] += xr[a][p + d] * K[j][p];
            }
        }

        float4 o;
        o.x = acc[0]; o.y = acc[1]; o.z = acc[2]; o.w = acc[3];
        *reinterpret_cast<float4*>(y + (size_t)b * plane + orow) = o;
    }
}

extern "C" void kernel_launch(void* const* d_in, const int* in_sizes, int n_in,
                              void* d_out, int out_size) {
    const float* image = (const float*)d_in[0];  // (1, 1024, 1024)
    const float* x     = (const float*)d_in[1];  // (8, 1, 1024, 1024)
    const float* klw   = (const float*)d_in[2];  // (9, 1, 3, 3)
    const float* klb   = (const float*)d_in[3];  // (9,)
    float* y = (float*)d_out;                    // (8, 1, 1024, 1024)

    dim3 block(128);
    dim3 grid(WW / 4 / 128, HH);  // (2, 1024)
    small_sm_block_kernel<<<grid, block>>>(image, x, klw, klb, y);
}

// round 3
// speedup vs baseline: 2.4178x; 2.4178x over previous
#include <cuda_runtime.h>
#include <cuda_bf16.h>

#define HH 1024
#define WW 1024
#define NB 8

// Load 6 consecutive values (cols w0-1 .. w0+4) from row hh of a (HH,WW) plane,
// zero-padded outside. One aligned LDG.128 + two predicated edge scalars.
// All three loads are independent (high MLP) — do NOT replace edges with
// shuffles; R2 showed that collapses memory-latency hiding.
__device__ __forceinline__ void load_row6(const float* __restrict__ base, int hh,
                                          int w0, float out[6]) {
    if (hh < 0 || hh >= HH) {
#pragma unroll
        for (int c = 0; c < 6; c++) out[c] = 0.0f;
        return;
    }
    const float* row = base + (size_t)hh * WW;
    float4 v = *reinterpret_cast<const float4*>(row + w0);
    out[1] = v.x; out[2] = v.y; out[3] = v.z; out[4] = v.w;
    out[0] = (w0 > 0) ? row[w0 - 1] : 0.0f;
    out[5] = (w0 + 4 < WW) ? row[w0 + 4] : 0.0f;
}

// Accumulate one 3x3 spatially-varying apply: rows r0..r0+2 of xr, kernel K.
__device__ __forceinline__ void apply3(const float xr[4][6], int r0,
                                       const float K[9][4], float acc[4]) {
#pragma unroll
    for (int a = 0; a < 3; a++) {
#pragma unroll
        for (int d = 0; d < 3; d++) {
            const int j = a * 3 + d;
#pragma unroll
            for (int p = 0; p < 4; p++) acc[p] += xr[r0 + a][p + d] * K[j][p];
        }
    }
}

__global__ void __launch_bounds__(128)
small_sm_block_kernel(const float* __restrict__ image,
                      const float* __restrict__ x,
                      const float* __restrict__ wgt,   // (9,1,3,3) = 81
                      const float* __restrict__ bias,  // (9,)
                      float* __restrict__ y) {
    __shared__ float sw[81];
    __shared__ float sb[9];
    int t = threadIdx.x;
    if (t < 81) sw[t] = wgt[t];
    if (t < 9)  sb[t] = bias[t];
    __syncthreads();

    const int h0 = blockIdx.y * 2;                         // output rows h0, h0+1
    const int w0 = (blockIdx.x * blockDim.x + t) * 4;

    // ---- image neighborhood: rows h0-1 .. h0+2, cols w0-1..w0+4 ----
    float img[4][6];
#pragma unroll
    for (int r = 0; r < 4; r++) load_row6(image, h0 - 1 + r, w0, img[r]);

    // ---- K0 (for row h0) from img[0..2], K1 (for row h0+1) from img[1..3] ----
    float K0[9][4], K1[9][4];
#pragma unroll
    for (int j = 0; j < 9; j++) {
        const float bj = sb[j];
#pragma unroll
        for (int p = 0; p < 4; p++) { K0[j][p] = bj; K1[j][p] = bj; }
#pragma unroll
        for (int a = 0; a < 3; a++) {
#pragma unroll
            for (int d = 0; d < 3; d++) {
                const float wv = sw[j * 9 + a * 3 + d];
#pragma unroll
                for (int p = 0; p < 4; p++) {
                    K0[j][p] += img[a][p + d] * wv;
                    K1[j][p] += img[a + 1][p + d] * wv;
                }
            }
        }
    }

    // ---- apply to all batches: 4 x-rows serve 2 output rows ----
    const size_t plane = (size_t)HH * WW;
    const size_t o0 = (size_t)h0 * WW + w0;
    const size_t o1 = o0 + WW;
#pragma unroll
    for (int b = 0; b < NB; b++) {
        const float* xb = x + (size_t)b * plane;
        float xr[4][6];
#pragma unroll
        for (int r = 0; r < 4; r++) load_row6(xb, h0 - 1 + r, w0, xr[r]);

        float acc0[4] = {0.f, 0.f, 0.f, 0.f};
        apply3(xr, 0, K0, acc0);
        float4 oA;
        oA.x = acc0[0]; oA.y = acc0[1]; oA.z = acc0[2]; oA.w = acc0[3];
        *reinterpret_cast<float4*>(y + (size_t)b * plane + o0) = oA;

        float acc1[4] = {0.f, 0.f, 0.f, 0.f};
        apply3(xr, 1, K1, acc1);
        float4 oB;
        oB.x = acc1[0]; oB.y = acc1[1]; oB.z = acc1[2]; oB.w = acc1[3];
        *reinterpret_cast<float4*>(y + (size_t)b * plane + o1) = oB;
    }
}

extern "C" void kernel_launch(void* const* d_in, const int* in_sizes, int n_in,
                              void* d_out, int out_size) {
    const float* image = (const float*)d_in[0];  // (1, 1024, 1024)
    const float* x     = (const float*)d_in[1];  // (8, 1, 1024, 1024)
    const float* klw   = (const float*)d_in[2];  // (9, 1, 3, 3)
    const float* klb   = (const float*)d_in[3];  // (9,)
    float* y = (float*)d_out;                    // (8, 1, 1024, 1024)

    dim3 block(128);
    dim3 grid(WW / 4 / 128, HH / 2);  // (2, 512)
    small_sm_block_kernel<<<grid, block>>>(image, x, klw, klb, y);
}

// round 4
// speedup vs baseline: 2.4473x; 1.0122x over previous
#include <cuda_runtime.h>
#include <cuda_bf16.h>

#define HH 1024
#define WW 1024
#define NB 8

typedef unsigned long long u64;

// ---- packed fp32x2 helpers (sm_103a FFMA2 path, PTX-only) ----
__device__ __forceinline__ u64 pk(float lo, float hi) {
    u64 r; asm("mov.b64 %0, {%1, %2};" : "=l"(r) : "f"(lo), "f"(hi)); return r;
}
__device__ __forceinline__ void upk(u64 v, float& lo, float& hi) {
    asm("mov.b64 {%0, %1}, %2;" : "=f"(lo), "=f"(hi) : "l"(v));
}
__device__ __forceinline__ u64 fma2(u64 a, u64 b, u64 c) {
    u64 d; asm("fma.rn.f32x2 %0, %1, %2, %3;" : "=l"(d) : "l"(a), "l"(b), "l"(c));
    return d;
}

// Load 6 consecutive values (cols w0-1 .. w0+4) from row hh of a (HH,WW) plane,
// zero-padded outside. One aligned LDG.128 + two predicated edge scalars.
// All three loads are independent (high MLP) — do NOT replace edges with
// shuffles; R2 showed the warp-wide data dependency collapses latency hiding.
__device__ __forceinline__ void load_row6(const float* __restrict__ base, int hh,
                                          int w0, float out[6]) {
    if (hh < 0 || hh >= HH) {
#pragma unroll
        for (int c = 0; c < 6; c++) out[c] = 0.0f;
        return;
    }
    const float* row = base + (size_t)hh * WW;
    float4 v = *reinterpret_cast<const float4*>(row + w0);
    out[1] = v.x; out[2] = v.y; out[3] = v.z; out[4] = v.w;
    out[0] = (w0 > 0) ? row[w0 - 1] : 0.0f;
    out[5] = (w0 + 4 < WW) ? row[w0 + 4] : 0.0f;
}

__global__ void __launch_bounds__(128, 4)
small_sm_block_kernel(const float* __restrict__ image,
                      const float* __restrict__ x,
                      const float* __restrict__ wgt,   // (9,1,3,3) = 81
                      const float* __restrict__ bias,  // (9,)
                      float* __restrict__ y) {
    // Weights/bias duplicated into packed 64-bit pairs once per block.
    __shared__ u64 sw2[81];
    __shared__ u64 sb2[9];
    int t = threadIdx.x;
    if (t < 81) { float w = wgt[t];  sw2[t] = pk(w, w); }
    if (t < 9)  { float b = bias[t]; sb2[t] = pk(b, b); }
    __syncthreads();

    const int h0 = blockIdx.y * 2;                    // output rows h0, h0+1
    const int w0 = (blockIdx.x * blockDim.x + t) * 4;

    // ---- image neighborhood rows h0-1..h0+2, packed into sliding pairs ----
    float img[4][6];
#pragma unroll
    for (int r = 0; r < 4; r++) load_row6(image, h0 - 1 + r, w0, img[r]);

    u64 ip[4][5];
#pragma unroll
    for (int r = 0; r < 4; r++)
#pragma unroll
        for (int c = 0; c < 5; c++) ip[r][c] = pk(img[r][c], img[r][c + 1]);

    // ---- per-pixel kernels, packed: K01 = (K[j][0],K[j][1]), K23 = (K[j][2],K[j][3])
    //      A = output row h0 (img rows 0-2), B = row h0+1 (img rows 1-3) ----
    u64 K01A[9], K23A[9], K01B[9], K23B[9];
#pragma unroll
    for (int j = 0; j < 9; j++) {
        u64 b2 = sb2[j];
        K01A[j] = b2; K23A[j] = b2; K01B[j] = b2; K23B[j] = b2;
#pragma unroll
        for (int a = 0; a < 3; a++)
#pragma unroll
            for (int d = 0; d < 3; d++) {
                u64 w2 = sw2[j * 9 + a * 3 + d];
                K01A[j] = fma2(ip[a][d],         w2, K01A[j]);
                K23A[j] = fma2(ip[a][d + 2],     w2, K23A[j]);
                K01B[j] = fma2(ip[a + 1][d],     w2, K01B[j]);
                K23B[j] = fma2(ip[a + 1][d + 2], w2, K23B[j]);
            }
    }

    // ---- apply to all batches: 4 x-rows serve 2 output rows ----
    const size_t plane = (size_t)HH * WW;
    const size_t o0 = (size_t)h0 * WW + w0;
#pragma unroll 2
    for (int b = 0; b < NB; b++) {
        const float* xb = x + (size_t)b * plane;
        float xr[4][6];
#pragma unroll
        for (int r = 0; r < 4; r++) load_row6(xb, h0 - 1 + r, w0, xr[r]);

        u64 xp[4][5];
#pragma unroll
        for (int r = 0; r < 4; r++)
#pragma unroll
            for (int c = 0; c < 5; c++) xp[r][c] = pk(xr[r][c], xr[r][c + 1]);

        u64 a01A = 0ull, a23A = 0ull, a01B = 0ull, a23B = 0ull;  // {+0.f,+0.f}
#pragma unroll
        for (int a = 0; a < 3; a++)
#pragma unroll
            for (int d = 0; d < 3; d++) {
                const int j = a * 3 + d;
                a01A = fma2(xp[a][d],         K01A[j], a01A);
                a23A = fma2(xp[a][d + 2],     K23A[j], a23A);
                a01B = fma2(xp[a + 1][d],     K01B[j], a01B);
                a23B = fma2(xp[a + 1][d + 2], K23B[j], a23B);
            }

        float4 oA, oB;
        upk(a01A, oA.x, oA.y); upk(a23A, oA.z, oA.w);
        upk(a01B, oB.x, oB.y); upk(a23B, oB.z, oB.w);
        *reinterpret_cast<float4*>(y + (size_t)b * plane + o0)      = oA;
        *reinterpret_cast<float4*>(y + (size_t)b * plane + o0 + WW) = oB;
    }
}

extern "C" void kernel_launch(void* const* d_in, const int* in_sizes, int n_in,
                              void* d_out, int out_size) {
    const float* image = (const float*)d_in[0];  // (1, 1024, 1024)
    const float* x     = (const float*)d_in[1];  // (8, 1, 1024, 1024)
    const float* klw   = (const float*)d_in[2];  // (9, 1, 3, 3)
    const float* klb   = (const float*)d_in[3];  // (9,)
    float* y = (float*)d_out;                    // (8, 1, 1024, 1024)

    dim3 block(128);
    dim3 grid(WW / 4 / 128, HH / 2);  // (2, 512)
    small_sm_block_kernel<<<grid, block>>>(image, x, klw, klb, y);
}